// round 6
// baseline (speedup 1.0000x reference)
#include <cuda_runtime.h>
#include <math.h>

// ---------------- problem constants ----------------
#define B_ 256
#define T_ 500
#define I_ 8
#define H_ 1024
#define O_ 8
#define ALPHA_ 0.2f
#define NSTD_ 0.05f

// ---------------- geometry ----------------
#define GRID_ 128          // 16 j-tiles x 8 batch-tiles, all co-resident
#define NTHR 256           // 8 warps; warp owns 8 j-columns; lane owns 1 batch elem
#define BM 32              // batch tile (= warp width)
#define BN 64              // j tile (8 warps x 8 cols)
#define COLS_W 8           // columns per warp
#define KSEG 256           // k segment size
#define NSEG 4             // 4 segments of 256 k
#define CAP 256            // max list entries per column (15% density -> ~154 avg)

// ---------------- smem layout (byte offsets) ----------------
#define LIST_OFF  0
#define LIST_BYTES (BN * CAP * 8)                 // 131072
#define SEGP_OFF  (LIST_OFF + LIST_BYTES)         // 131072
#define SEGP_BYTES (BN * 5 * 4)                   // 1280
#define RBUF_OFF  (SEGP_OFF + SEGP_BYTES)         // 132352 (16B aligned)
#define RSEG_BYTES (KSEG * BM * 4)                // 32768
#define RBUF_BYTES (2 * RSEG_BYTES)               // 65536
#define WIS_OFF   (RBUF_OFF + RBUF_BYTES)         // 197888
#define WIS_BYTES (BN * I_ * 4)                   // 2048
#define WOUT_OFF  (WIS_OFF + WIS_BYTES)           // 199936
#define WOUT_BYTES (BN * O_ * 4)                  // 2048
#define OUTST_OFF (WOUT_OFF + WOUT_BYTES)         // 201984
#define OUTST_BYTES (8 * BM * O_ * 4)             // 8192
#define SMEM_BYTES (OUTST_OFF + OUTST_BYTES)      // 210176

// ---------------- device scratch (no allocations) ----------------
__device__ float g_M[H_ * H_];                // staging: M[k][j] = relu(g[k])*effW[j][k]
__device__ int2  g_list[H_ * CAP];            // per-column compacted (byte_off, val_bits)
__device__ int   g_segptr[H_ * 5];            // per-column local segment starts + end
__device__ float g_rA[H_ * B_];               // r buffers, TRANSPOSED layout [h][b]
__device__ float g_rB[H_ * B_];
__device__ float g_outp[2 * 16 * B_ * O_];    // per-jtile output partials, double buffered
__device__ float g_out0[O_];
__device__ unsigned g_bar;

__device__ __forceinline__ float softplus_f(float v) {
    return fmaxf(v, 0.0f) + log1pf(expf(-fabsf(v)));
}

__device__ __forceinline__ void cp16(unsigned dst, const void* src) {
    asm volatile("cp.async.cg.shared.global [%0], [%1], 16;" :: "r"(dst), "l"(src));
}

// ---------------- setup kernels ----------------

__global__ void k_reset() { g_bar = 0u; }

__global__ void k_build_M(const float* __restrict__ wrec, const float* __restrict__ mwrec,
                          const float* __restrict__ refEI, const float* __restrict__ g) {
    int n = blockIdx.x * blockDim.x + threadIdx.x;   // n = j*H + k
    if (n >= H_ * H_) return;
    int j = n >> 10;
    int k = n & (H_ - 1);
    float ei = refEI[k];               // row 0 of refEI = ei (exactly +/-1)
    float w  = wrec[n];                // wrec[j][k]
    float e = fmaxf(w * ei, 0.0f) * ei * mwrec[n];   // effW[j][k]; (|ei|-1) term is exactly 0
    g_M[k * H_ + j] = fmaxf(g[k], 0.0f) * e;
}

// one thread per column j: compact nonzeros of column j, segmented by k/256,
// each segment start padded to an EVEN index (16B alignment for int4 loads).
__global__ void k_build_list() {
    int j = blockIdx.x * blockDim.x + threadIdx.x;
    if (j >= H_) return;
    int idx = 0;
    for (int s = 0; s < NSEG; ++s) {
        if (idx & 1) { g_list[j * CAP + idx] = make_int2(0, 0); idx++; }  // pad prev seg
        g_segptr[j * 5 + s] = idx;
        int kbase = s * KSEG;
        for (int k = kbase; k < kbase + KSEG; ++k) {
            float v = g_M[k * H_ + j];                 // coalesced across threads j
            if (v != 0.0f && idx < CAP) {
                g_list[j * CAP + idx] = make_int2((k - kbase) * (BM * 4), __float_as_int(v));
                idx++;
            }
        }
    }
    g_segptr[j * 5 + 4] = idx;
}

__global__ void k_init_r(const float* __restrict__ h0, const float* __restrict__ bvec) {
    int n = blockIdx.x * blockDim.x + threadIdx.x;   // layout [h][b]
    if (n >= H_ * B_) return;
    int hh = n >> 8;
    g_rA[n] = softplus_f(h0[hh] + bvec[hh]);
}

__global__ void k_out0(const float* __restrict__ h0, const float* __restrict__ bvec,
                       const float* __restrict__ wout) {
    int tid = threadIdx.x;
    float p[O_];
#pragma unroll
    for (int o = 0; o < O_; ++o) p[o] = 0.0f;
    for (int hh = tid; hh < H_; hh += 256) {
        float r0 = softplus_f(h0[hh] + bvec[hh]);
#pragma unroll
        for (int o = 0; o < O_; ++o) p[o] += r0 * wout[hh * O_ + o];
    }
#pragma unroll
    for (int d = 16; d > 0; d >>= 1)
#pragma unroll
        for (int o = 0; o < O_; ++o) p[o] += __shfl_xor_sync(0xffffffffu, p[o], d);
    __shared__ float ws[8][O_];
    if ((tid & 31) == 0)
        for (int o = 0; o < O_; ++o) ws[tid >> 5][o] = p[o];
    __syncthreads();
    if (tid < O_) {
        float s = 0.0f;
        for (int w = 0; w < 8; ++w) s += ws[w][tid];
        g_out0[tid] = s;
    }
}

__global__ void k_fill0(float* __restrict__ out) {
    int n = blockIdx.x * blockDim.x + threadIdx.x;   // over B*O
    if (n >= B_ * O_) return;
    out[(size_t)(n >> 3) * (T_ * O_) + (n & 7)] = g_out0[n & 7];   // t = 0
}

// ---------------- persistent sparse RNN kernel ----------------

__global__ void __launch_bounds__(NTHR, 1)
k_rnn(const float* __restrict__ x, const float* __restrict__ noise,
      const float* __restrict__ wi, const float* __restrict__ wout,
      const float* __restrict__ bvec, const float* __restrict__ h0,
      float* __restrict__ out)
{
    extern __shared__ char smc[];
    int2*  sm_list = (int2*)(smc + LIST_OFF);
    int*   sm_segp = (int*)(smc + SEGP_OFF);
    float* sm_wis  = (float*)(smc + WIS_OFF);
    float* sm_wout = (float*)(smc + WOUT_OFF);
    float* sm_outst= (float*)(smc + OUTST_OFF);

    const int tid  = threadIdx.x;
    const int lane = tid & 31;
    const int w    = tid >> 5;              // warp 0..7
    const int cta  = blockIdx.x;
    const int jtile = cta & 15;             // 0..15
    const int btile = cta >> 4;             // 0..7
    const int j0 = jtile * BN;
    const int b0 = btile * BM;
    const int c0 = w * COLS_W;              // local column base for this warp
    const int jc0 = j0 + c0;                // global column base

    // ---- one-time staging: lists (128KB), segment pointers, wi, wout ----
    {
        const int4* Lg = (const int4*)(g_list + (size_t)j0 * CAP);
        int4* Ls = (int4*)sm_list;
        for (int n = tid; n < BN * CAP / 2; n += NTHR) Ls[n] = __ldg(Lg + n);
        for (int n = tid; n < BN * 5; n += NTHR) {
            int c = n / 5, s = n - c * 5;
            sm_segp[n] = c * CAP + g_segptr[(j0 + c) * 5 + s];   // absolute into sm_list
        }
        for (int n = tid; n < BN * I_; n += NTHR) {
            int c = n >> 3, i = n & 7;
            sm_wis[n] = wi[i * H_ + j0 + c];                      // [c][i]
        }
        for (int n = tid; n < BN * O_; n += NTHR)
            sm_wout[n] = wout[(size_t)j0 * O_ + n];               // [c][o]
    }

    float bT[COLS_W], h[COLS_W];
#pragma unroll
    for (int cc = 0; cc < COLS_W; ++cc) {
        bT[cc] = bvec[jc0 + cc];
        h[cc]  = h0[jc0 + cc];
    }
    __syncthreads();

    const unsigned rs_sh = (unsigned)__cvta_generic_to_shared(smc + RBUF_OFF);
    unsigned epoch = 0;

    for (int t = 0; t < T_ - 1; ++t) {
        const float* __restrict__ Rg = (t & 1) ? g_rB : g_rA;
        float* __restrict__       Rn = (t & 1) ? g_rA : g_rB;

        // ---- prefetch segment 0 into buffer 0 ----
#pragma unroll
        for (int p = 0; p < 8; ++p) {
            int idx = p * NTHR + tid;                 // 2048 chunks of 16B
            int row = idx >> 3, piece = idx & 7;
            cp16(rs_sh + (unsigned)((row * BM + piece * 4) << 2),
                 Rg + (size_t)row * B_ + b0 + piece * 4);
        }
        asm volatile("cp.async.commit_group;" ::: "memory");

        // ---- prefetch noise & x for this (b=lane, cols jc0..jc0+7) ----
        float4 nza = __ldcg((const float4*)(noise + (size_t)(b0 + lane) * (T_ * H_)
                                            + (size_t)t * H_ + jc0));
        float4 nzb = __ldcg((const float4*)(noise + (size_t)(b0 + lane) * (T_ * H_)
                                            + (size_t)t * H_ + jc0 + 4));
        float4 xa  = __ldcg((const float4*)(x + (size_t)(b0 + lane) * (T_ * I_)
                                            + (size_t)t * I_));
        float4 xb  = __ldcg((const float4*)(x + (size_t)(b0 + lane) * (T_ * I_)
                                            + (size_t)t * I_ + 4));

        // ---- deterministic reduce of PREVIOUS step's output partials ----
        if (t >= 1 && tid < 16) {
            int P = cta * 16 + tid;                              // b*8+o in [0,2048)
            const float* src = g_outp + (size_t)((t - 1) & 1) * (16 * B_ * O_);
            float s = 0.0f;
#pragma unroll
            for (int jt = 0; jt < 16; ++jt) s += __ldcv(src + jt * (B_ * O_) + P);
            out[(size_t)(P >> 3) * (T_ * O_) + (size_t)t * O_ + (P & 7)] = s;
        }

        float acc[COLS_W];
#pragma unroll
        for (int cc = 0; cc < COLS_W; ++cc) acc[cc] = 0.0f;

        // ---- sparse GEMM over 4 k-segments ----
#pragma unroll 1
        for (int s = 0; s < NSEG; ++s) {
            asm volatile("cp.async.wait_group 0;" ::: "memory");
            __syncthreads();                 // segment s resident; buffer s-1 free
            if (s + 1 < NSEG) {
                const int nb = (s + 1) & 1;
                const int k0 = (s + 1) * KSEG;
#pragma unroll
                for (int p = 0; p < 8; ++p) {
                    int idx = p * NTHR + tid;
                    int row = idx >> 3, piece = idx & 7;
                    cp16(rs_sh + (unsigned)(nb * RSEG_BYTES) +
                         (unsigned)((row * BM + piece * 4) << 2),
                         Rg + (size_t)(k0 + row) * B_ + b0 + piece * 4);
                }
                asm volatile("cp.async.commit_group;" ::: "memory");
            }

            const char* rb = smc + RBUF_OFF + (s & 1) * RSEG_BYTES + lane * 4;
            const int4* L4 = (const int4*)sm_list;
#pragma unroll
            for (int cc = 0; cc < COLS_W; ++cc) {
                const int c = c0 + cc;
                int n  = sm_segp[c * 5 + s];       // even (padded)
                const int pe = sm_segp[c * 5 + s + 1];
                float a0 = 0.f, a1 = 0.f, a2 = 0.f, a3 = 0.f;
                for (; n + 8 <= pe; n += 8) {
                    int4 A = L4[(n >> 1)],     Bq = L4[(n >> 1) + 1];
                    int4 C = L4[(n >> 1) + 2], D  = L4[(n >> 1) + 3];
                    a0 += *(const float*)(rb + A.x)  * __int_as_float(A.y);
                    a1 += *(const float*)(rb + A.z)  * __int_as_float(A.w);
                    a2 += *(const float*)(rb + Bq.x) * __int_as_float(Bq.y);
                    a3 += *(const float*)(rb + Bq.z) * __int_as_float(Bq.w);
                    a0 += *(const float*)(rb + C.x)  * __int_as_float(C.y);
                    a1 += *(const float*)(rb + C.z)  * __int_as_float(C.w);
                    a2 += *(const float*)(rb + D.x)  * __int_as_float(D.y);
                    a3 += *(const float*)(rb + D.z)  * __int_as_float(D.w);
                }
                for (; n + 2 <= pe; n += 2) {
                    int4 A = L4[(n >> 1)];
                    a0 += *(const float*)(rb + A.x) * __int_as_float(A.y);
                    a1 += *(const float*)(rb + A.z) * __int_as_float(A.w);
                }
                if (n < pe) {
                    int2 e = sm_list[n];
                    a0 += *(const float*)(rb + e.x) * __int_as_float(e.y);
                }
                acc[cc] += (a0 + a1) + (a2 + a3);
            }
        }

        // ---- input projection ----
        float inp[COLS_W];
#pragma unroll
        for (int cc = 0; cc < COLS_W; ++cc) {
            const float* wv = sm_wis + (c0 + cc) * I_;
            float4 wA = *(const float4*)wv;
            float4 wB = *(const float4*)(wv + 4);
            inp[cc] = xa.x * wA.x + xa.y * wA.y + xa.z * wA.z + xa.w * wA.w
                    + xb.x * wB.x + xb.y * wB.y + xb.z * wB.z + xb.w * wB.w;
        }

        float nzv[COLS_W] = {nza.x, nza.y, nza.z, nza.w, nzb.x, nzb.y, nzb.z, nzb.w};

        // ---- state update + softplus + r write ----
        float rn[COLS_W];
#pragma unroll
        for (int cc = 0; cc < COLS_W; ++cc) {
            float hv = h[cc];
            hv = hv + NSTD_ * nzv[cc] + ALPHA_ * (-hv + acc[cc] + inp[cc]);
            h[cc] = hv;
            float rv = softplus_f(hv + bT[cc]);
            rn[cc] = rv;
            Rn[(size_t)(jc0 + cc) * B_ + b0 + lane] = rv;   // coalesced 128B per column
        }

        // ---- output partials p[o] over this warp's 8 columns ----
        float p[O_];
#pragma unroll
        for (int o = 0; o < O_; ++o) p[o] = 0.0f;
#pragma unroll
        for (int cc = 0; cc < COLS_W; ++cc) {
            const float* wv = sm_wout + (c0 + cc) * O_;
            float4 wo0 = *(const float4*)wv;
            float4 wo1 = *(const float4*)(wv + 4);
            float rv = rn[cc];
            p[0] += rv * wo0.x; p[1] += rv * wo0.y; p[2] += rv * wo0.z; p[3] += rv * wo0.w;
            p[4] += rv * wo1.x; p[5] += rv * wo1.y; p[6] += rv * wo1.z; p[7] += rv * wo1.w;
        }
        {
            float4* st = (float4*)(sm_outst + ((size_t)w * BM + lane) * O_);
            st[0] = make_float4(p[0], p[1], p[2], p[3]);
            st[1] = make_float4(p[4], p[5], p[6], p[7]);
        }
        __syncthreads();
        {
            int brel = tid >> 3, o = tid & 7;       // 256 threads = 32 b x 8 o
            float ssum = 0.0f;
#pragma unroll
            for (int ww = 0; ww < 8; ++ww) ssum += sm_outst[((size_t)ww * BM + brel) * O_ + o];
            g_outp[(size_t)(t & 1) * (16 * B_ * O_) + (size_t)jtile * (B_ * O_)
                   + (size_t)(b0 + brel) * O_ + o] = ssum;
        }

        // ---- grid barrier ----
        epoch++;
        __syncthreads();
        if (tid == 0) {
            __threadfence();
            atomicAdd(&g_bar, 1u);
            const unsigned target = epoch * GRID_;
            while (*(volatile unsigned*)&g_bar < target) __nanosleep(32);
        }
        __syncthreads();
    }

    // ---- final output reduce (step T-2 -> out[:, T-1, :]) ----
    if (tid < 16) {
        int P = cta * 16 + tid;
        const float* src = g_outp + (size_t)((T_ - 2) & 1) * (16 * B_ * O_);
        float s = 0.0f;
#pragma unroll
        for (int jt = 0; jt < 16; ++jt) s += __ldcv(src + jt * (B_ * O_) + P);
        out[(size_t)(P >> 3) * (T_ * O_) + (size_t)(T_ - 1) * O_ + (P & 7)] = s;
    }
}

// ---------------- launch ----------------

extern "C" void kernel_launch(void* const* d_in, const int* in_sizes, int n_in,
                              void* d_out, int out_size) {
    const float* x     = (const float*)d_in[0];
    const float* noise = (const float*)d_in[1];
    const float* wi    = (const float*)d_in[2];
    const float* wrec  = (const float*)d_in[3];
    const float* wout  = (const float*)d_in[4];
    const float* bvec  = (const float*)d_in[5];
    const float* g     = (const float*)d_in[6];
    const float* h0    = (const float*)d_in[7];
    const float* refEI = (const float*)d_in[8];
    const float* mwrec = (const float*)d_in[9];
    float* out = (float*)d_out;

    cudaFuncSetAttribute(k_rnn, cudaFuncAttributeMaxDynamicSharedMemorySize, SMEM_BYTES);

    k_reset<<<1, 1>>>();
    k_build_M<<<(H_ * H_ + 255) / 256, 256>>>(wrec, mwrec, refEI, g);
    k_build_list<<<(H_ + 255) / 256, 256>>>();
    k_init_r<<<(H_ * B_ + 255) / 256, 256>>>(h0, bvec);
    k_out0<<<1, 256>>>(h0, bvec, wout);
    k_fill0<<<(B_ * O_ + 255) / 256, 256>>>(out);
    k_rnn<<<GRID_, NTHR, SMEM_BYTES>>>(x, noise, wi, wout, bvec, h0, out);
}

// round 7
// speedup vs baseline: 1.2017x; 1.2017x over previous
#include <cuda_runtime.h>
#include <math.h>

// ---------------- problem constants ----------------
#define B_ 256
#define T_ 500
#define I_ 8
#define H_ 1024
#define O_ 8
#define ALPHA_ 0.2f
#define NSTD_ 0.05f

// ---------------- geometry ----------------
#define GRID_ 128          // 16 j-tiles x 8 batch-tiles, all co-resident
#define NTHR 512           // 16 warps; warp owns 4 j-columns; lane owns 1 batch elem
#define NWARP 16
#define BM 32              // batch tile (= warp width)
#define BN 64              // j tile (16 warps x 4 cols)
#define COLS_W 4
#define KSEG 256
#define NSEG 4
#define JT_QCAP 3584       // quads per j-tile (avg need ~2850; 16 sd headroom)

// ---------------- smem layout (byte offsets) ----------------
#define LIST_OFF  0
#define LIST_BYTES (JT_QCAP * 32)                 // 114688
#define TAB_OFF   (LIST_OFF + LIST_BYTES)
#define TAB_BYTES (NWARP * NSEG * 8)              // 512 (int2 per (group,seg))
#define RBUF_OFF  (TAB_OFF + TAB_BYTES)           // 115200 (16B aligned)
#define RSEG_BYTES (KSEG * BM * 4)                // 32768
#define RBUF_BYTES (2 * RSEG_BYTES)               // 65536
#define WIS_OFF   (RBUF_OFF + RBUF_BYTES)
#define WIS_BYTES (BN * I_ * 4)                   // 2048
#define WOUT_OFF  (WIS_OFF + WIS_BYTES)
#define WOUT_BYTES (BN * O_ * 4)                  // 2048
#define OUTST_OFF (WOUT_OFF + WOUT_BYTES)
#define OUTST_BYTES (NWARP * BM * O_ * 4)         // 16384
#define SMEM_BYTES (OUTST_OFF + OUTST_BYTES)      // 201216

// ---------------- device scratch (no allocations) ----------------
__device__ float g_M[H_ * H_];                 // M[k][j] = relu(g[k])*effW[j][k]
__device__ int2  g_qlist[16 * JT_QCAP * 4];    // per-jtile interleaved quads [n][c]
__device__ int   g_qoff[16 * 64];              // per (jtile, group*4+seg) start quad
__device__ int   g_qcnt[16 * 64];              // per (jtile, group*4+seg) quad count
__device__ float g_rA[H_ * B_];                // r buffers, TRANSPOSED [h][b]
__device__ float g_rB[H_ * B_];
__device__ float g_outp[2 * 16 * B_ * O_];     // per-jtile output partials, dbl buf
__device__ unsigned g_bar;

__device__ __forceinline__ float softplus_f(float v) {
    return fmaxf(v, 0.0f) + log1pf(expf(-fabsf(v)));
}

__device__ __forceinline__ void cp16(unsigned dst, const void* src) {
    asm volatile("cp.async.cg.shared.global [%0], [%1], 16;" :: "r"(dst), "l"(src));
}

// ---------------- setup kernel 0: build M (+ reset barrier) ----------------

__global__ void k_build_M(const float* __restrict__ wrec, const float* __restrict__ mwrec,
                          const float* __restrict__ refEI, const float* __restrict__ g) {
    int n = blockIdx.x * blockDim.x + threadIdx.x;   // n = j*H + k
    if (n == 0) g_bar = 0u;
    if (n >= H_ * H_) return;
    int j = n >> 10;
    int k = n & (H_ - 1);
    float ei = refEI[k];               // row 0 of refEI = ei (exactly +/-1)
    float w  = wrec[n];                // wrec[j][k]
    float e = fmaxf(w * ei, 0.0f) * ei * mwrec[n];   // effW[j][k]; (|ei|-1) term exactly 0
    g_M[k * H_ + j] = fmaxf(g[k], 0.0f) * e;
}

// ---------------- setup kernel 1: counts + prefix (single block, 1024 thr) ----

__global__ void k_setup_counts() {
    __shared__ int cnts[1024];
    int tid = threadIdx.x;                 // tid = gq*4 + s, gq in [0,256), s in [0,4)
    int gq = tid >> 2;
    int s  = tid & 3;
    int j0 = gq * 4;
    int c0 = 0, c1 = 0, c2 = 0, c3 = 0;
    for (int k = s * KSEG; k < (s + 1) * KSEG; ++k) {
        float4 v = *(const float4*)(g_M + (size_t)k * H_ + j0);
        c0 += (v.x != 0.0f); c1 += (v.y != 0.0f);
        c2 += (v.z != 0.0f); c3 += (v.w != 0.0f);
    }
    cnts[tid] = max(max(c0, c1), max(c2, c3));
    __syncthreads();
    if (tid < 16) {                        // per-jtile exclusive prefix over 64 slots
        int jt = tid, total = 0;
        for (int idx = 0; idx < 64; ++idx) {
            int c = cnts[jt * 64 + idx];
            if (total + c > JT_QCAP) c = JT_QCAP - total;   // defensive clamp
            g_qoff[jt * 64 + idx] = total;
            g_qcnt[jt * 64 + idx] = c;
            total += c;
        }
    }
}

// ---------------- setup kernel 2: fill lists + init r + out0/fill0 ----------

__global__ void k_setup_rest(const float* __restrict__ h0, const float* __restrict__ bvec,
                             const float* __restrict__ wout, float* __restrict__ out) {
    int blk = blockIdx.x;
    int tid = threadIdx.x;
    if (blk < 16) {
        // fill interleaved list for jtile = blk; thread = (g, s, c)
        int jt = blk;
        int c  = tid & 3;
        int s  = (tid >> 2) & 3;
        int g  = tid >> 4;                 // 0..15
        int j  = jt * BN + g * 4 + c;
        int slot = g * 4 + s;
        int base = g_qoff[jt * 64 + slot];
        int cnt  = g_qcnt[jt * 64 + slot];
        int2* dst = g_qlist + (size_t)jt * (JT_QCAP * 4);
        int n = 0;
        for (int k = 0; k < KSEG && n < cnt; ++k) {
            float v = g_M[(size_t)(s * KSEG + k) * H_ + j];
            if (v != 0.0f) {
                dst[(size_t)(base + n) * 4 + c] = make_int2(k * (BM * 4), __float_as_int(v));
                n++;
            }
        }
        for (; n < cnt; ++n)               // pad: +0.0*r[0] (exact no-op)
            dst[(size_t)(base + n) * 4 + c] = make_int2(0, 0);
    } else if (blk < 16 + 1024) {
        int n = (blk - 16) * 256 + tid;    // H*B, layout [h][b]
        int hh = n >> 8;
        g_rA[n] = softplus_f(h0[hh] + bvec[hh]);
    } else {
        // out0 + fill t=0 (single block of 256)
        __shared__ float ws[8][O_];
        __shared__ float o0[O_];
        float p[O_];
#pragma unroll
        for (int o = 0; o < O_; ++o) p[o] = 0.0f;
        for (int hh = tid; hh < H_; hh += 256) {
            float r0 = softplus_f(h0[hh] + bvec[hh]);
#pragma unroll
            for (int o = 0; o < O_; ++o) p[o] += r0 * wout[hh * O_ + o];
        }
#pragma unroll
        for (int d = 16; d > 0; d >>= 1)
#pragma unroll
            for (int o = 0; o < O_; ++o) p[o] += __shfl_xor_sync(0xffffffffu, p[o], d);
        if ((tid & 31) == 0)
            for (int o = 0; o < O_; ++o) ws[tid >> 5][o] = p[o];
        __syncthreads();
        if (tid < O_) {
            float sv = 0.0f;
            for (int w = 0; w < 8; ++w) sv += ws[w][tid];
            o0[tid] = sv;
        }
        __syncthreads();
        for (int rep = 0; rep < 8; ++rep) {
            int P = rep * 256 + tid;       // b*8 + o
            out[(size_t)(P >> 3) * (T_ * O_) + (P & 7)] = o0[P & 7];
        }
    }
}

// ---------------- persistent sparse RNN kernel ----------------

__global__ void __launch_bounds__(NTHR, 1)
k_rnn(const float* __restrict__ x, const float* __restrict__ noise,
      const float* __restrict__ wi, const float* __restrict__ wout,
      const float* __restrict__ bvec, const float* __restrict__ h0,
      float* __restrict__ out)
{
    extern __shared__ char smc[];
    int2*  sm_tab  = (int2*)(smc + TAB_OFF);
    float* sm_wis  = (float*)(smc + WIS_OFF);
    float* sm_wout = (float*)(smc + WOUT_OFF);
    float* sm_outst= (float*)(smc + OUTST_OFF);

    const int tid  = threadIdx.x;
    const int lane = tid & 31;
    const int w    = tid >> 5;              // warp = column group 0..15
    const int cta  = blockIdx.x;
    const int jtile = cta & 15;
    const int btile = cta >> 4;
    const int j0 = jtile * BN;
    const int b0 = btile * BM;
    const int jc0 = j0 + w * COLS_W;

    // ---- one-time staging ----
    {
        const int4* Lg = (const int4*)(g_qlist + (size_t)jtile * (JT_QCAP * 4));
        int4* Ls = (int4*)(smc + LIST_OFF);
        for (int n = tid; n < JT_QCAP * 2; n += NTHR) Ls[n] = __ldg(Lg + n);
        if (tid < 64)
            sm_tab[tid] = make_int2(g_qoff[jtile * 64 + tid], g_qcnt[jtile * 64 + tid]);
        // wis[c][i], wout[c][o]
        {
            int c = tid >> 3, i = tid & 7;                   // 512 = 64*8
            sm_wis[tid]  = wi[i * H_ + j0 + c];
            sm_wout[tid] = wout[(size_t)j0 * O_ + tid];
        }
    }

    float bT[COLS_W], h[COLS_W];
#pragma unroll
    for (int cc = 0; cc < COLS_W; ++cc) {
        bT[cc] = bvec[jc0 + cc];
        h[cc]  = h0[jc0 + cc];
    }
    __syncthreads();

    const unsigned rs_sh = (unsigned)__cvta_generic_to_shared(smc + RBUF_OFF);
    unsigned epoch = 0;

    for (int t = 0; t < T_ - 1; ++t) {
        const float* __restrict__ Rg = (t & 1) ? g_rB : g_rA;
        float* __restrict__       Rn = (t & 1) ? g_rA : g_rB;

        // ---- prefetch segment 0 into buffer 0 ----
#pragma unroll
        for (int p = 0; p < 4; ++p) {
            int idx = p * NTHR + tid;                 // 2048 chunks of 16B
            int row = idx >> 3, piece = idx & 7;
            cp16(rs_sh + (unsigned)((row * BM + piece * 4) << 2),
                 Rg + (size_t)row * B_ + b0 + piece * 4);
        }
        asm volatile("cp.async.commit_group;" ::: "memory");

        // ---- prefetch noise & x (b = lane, this warp's 4 cols) ----
        float4 nz4 = __ldcg((const float4*)(noise + (size_t)(b0 + lane) * (T_ * H_)
                                            + (size_t)t * H_ + jc0));
        float4 xa  = __ldcg((const float4*)(x + (size_t)(b0 + lane) * (T_ * I_)
                                            + (size_t)t * I_));
        float4 xb  = __ldcg((const float4*)(x + (size_t)(b0 + lane) * (T_ * I_)
                                            + (size_t)t * I_ + 4));

        // ---- deterministic reduce of PREVIOUS step's output partials ----
        if (t >= 1 && tid < 16) {
            int P = cta * 16 + tid;                              // b*8+o
            const float* src = g_outp + (size_t)((t - 1) & 1) * (16 * B_ * O_);
            float s = 0.0f;
#pragma unroll
            for (int jt = 0; jt < 16; ++jt) s += __ldcv(src + jt * (B_ * O_) + P);
            out[(size_t)(P >> 3) * (T_ * O_) + (size_t)t * O_ + (P & 7)] = s;
        }

        float acc[COLS_W] = {0.f, 0.f, 0.f, 0.f};

        // ---- sparse GEMM over 4 k-segments ----
#pragma unroll 1
        for (int s = 0; s < NSEG; ++s) {
            asm volatile("cp.async.wait_group 0;" ::: "memory");
            __syncthreads();                 // segment s resident; buffer s-1 free
            if (s + 1 < NSEG) {
                const int nb = (s + 1) & 1;
                const int k0 = (s + 1) * KSEG;
#pragma unroll
                for (int p = 0; p < 4; ++p) {
                    int idx = p * NTHR + tid;
                    int row = idx >> 3, piece = idx & 7;
                    cp16(rs_sh + (unsigned)(nb * RSEG_BYTES) +
                         (unsigned)((row * BM + piece * 4) << 2),
                         Rg + (size_t)(k0 + row) * B_ + b0 + piece * 4);
                }
                asm volatile("cp.async.commit_group;" ::: "memory");
            }

            const char* rb = smc + RBUF_OFF + (s & 1) * RSEG_BYTES + lane * 4;
            const int2 tb = sm_tab[w * 4 + s];
            const int4* Lq = ((const int4*)(smc + LIST_OFF)) + tb.x * 2;
            const int cnt = tb.y;
            // 4 independent indirect LDS->FFMA chains (one per column)
#pragma unroll 2
            for (int n = 0; n < cnt; ++n) {
                int4 A = Lq[2 * n];
                int4 Bv = Lq[2 * n + 1];
                acc[0] += *(const float*)(rb + A.x)  * __int_as_float(A.y);
                acc[1] += *(const float*)(rb + A.z)  * __int_as_float(A.w);
                acc[2] += *(const float*)(rb + Bv.x) * __int_as_float(Bv.y);
                acc[3] += *(const float*)(rb + Bv.z) * __int_as_float(Bv.w);
            }
        }

        // ---- input projection ----
        float inp[COLS_W];
#pragma unroll
        for (int cc = 0; cc < COLS_W; ++cc) {
            const float* wv = sm_wis + (w * COLS_W + cc) * I_;
            float4 wA = *(const float4*)wv;
            float4 wB = *(const float4*)(wv + 4);
            inp[cc] = xa.x * wA.x + xa.y * wA.y + xa.z * wA.z + xa.w * wA.w
                    + xb.x * wB.x + xb.y * wB.y + xb.z * wB.z + xb.w * wB.w;
        }

        float nzv[COLS_W] = {nz4.x, nz4.y, nz4.z, nz4.w};

        // ---- state update + softplus + r write ----
        float rn[COLS_W];
#pragma unroll
        for (int cc = 0; cc < COLS_W; ++cc) {
            float hv = h[cc];
            hv = hv + NSTD_ * nzv[cc] + ALPHA_ * (-hv + acc[cc] + inp[cc]);
            h[cc] = hv;
            float rv = softplus_f(hv + bT[cc]);
            rn[cc] = rv;
            Rn[(size_t)(jc0 + cc) * B_ + b0 + lane] = rv;   // coalesced 128B per column
        }

        // ---- output partials over this warp's 4 columns ----
        float p[O_];
#pragma unroll
        for (int o = 0; o < O_; ++o) p[o] = 0.0f;
#pragma unroll
        for (int cc = 0; cc < COLS_W; ++cc) {
            const float* wv = sm_wout + (w * COLS_W + cc) * O_;
            float4 wo0 = *(const float4*)wv;
            float4 wo1 = *(const float4*)(wv + 4);
            float rv = rn[cc];
            p[0] += rv * wo0.x; p[1] += rv * wo0.y; p[2] += rv * wo0.z; p[3] += rv * wo0.w;
            p[4] += rv * wo1.x; p[5] += rv * wo1.y; p[6] += rv * wo1.z; p[7] += rv * wo1.w;
        }
        {
            float4* st = (float4*)(sm_outst + ((size_t)w * BM + lane) * O_);
            st[0] = make_float4(p[0], p[1], p[2], p[3]);
            st[1] = make_float4(p[4], p[5], p[6], p[7]);
        }
        __syncthreads();
        if (tid < 256) {
            int brel = tid >> 3, o = tid & 7;       // 32 b x 8 o
            float ssum = 0.0f;
#pragma unroll
            for (int ww = 0; ww < NWARP; ++ww)
                ssum += sm_outst[((size_t)ww * BM + brel) * O_ + o];
            g_outp[(size_t)(t & 1) * (16 * B_ * O_) + (size_t)jtile * (B_ * O_)
                   + (size_t)(b0 + brel) * O_ + o] = ssum;
        }

        // ---- grid barrier ----
        epoch++;
        __syncthreads();
        if (tid == 0) {
            __threadfence();
            atomicAdd(&g_bar, 1u);
            const unsigned target = epoch * GRID_;
            while (*(volatile unsigned*)&g_bar < target) __nanosleep(32);
        }
        __syncthreads();
    }

    // ---- final output reduce (step T-2 -> out[:, T-1, :]) ----
    if (tid < 16) {
        int P = cta * 16 + tid;
        const float* src = g_outp + (size_t)((T_ - 2) & 1) * (16 * B_ * O_);
        float s = 0.0f;
#pragma unroll
        for (int jt = 0; jt < 16; ++jt) s += __ldcv(src + jt * (B_ * O_) + P);
        out[(size_t)(P >> 3) * (T_ * O_) + (size_t)(T_ - 1) * O_ + (P & 7)] = s;
    }
}

// ---------------- launch (exactly 4 kernels; k_rnn at launch index 3) ---------

extern "C" void kernel_launch(void* const* d_in, const int* in_sizes, int n_in,
                              void* d_out, int out_size) {
    const float* x     = (const float*)d_in[0];
    const float* noise = (const float*)d_in[1];
    const float* wi    = (const float*)d_in[2];
    const float* wrec  = (const float*)d_in[3];
    const float* wout  = (const float*)d_in[4];
    const float* bvec  = (const float*)d_in[5];
    const float* g     = (const float*)d_in[6];
    const float* h0    = (const float*)d_in[7];
    const float* refEI = (const float*)d_in[8];
    const float* mwrec = (const float*)d_in[9];
    float* out = (float*)d_out;

    cudaFuncSetAttribute(k_rnn, cudaFuncAttributeMaxDynamicSharedMemorySize, SMEM_BYTES);

    k_build_M<<<(H_ * H_ + 255) / 256, 256>>>(wrec, mwrec, refEI, g);
    k_setup_counts<<<1, 1024>>>();
    k_setup_rest<<<16 + 1024 + 1, 256>>>(h0, bvec, wout, out);
    k_rnn<<<GRID_, NTHR, SMEM_BYTES>>>(x, noise, wi, wout, bvec, h0, out);
}